// round 7
// baseline (speedup 1.0000x reference)
#include <cuda_runtime.h>
#include <cuda_bf16.h>
#include <cstdint>
#include <math.h>

#define CAP_E 655360
#define CAP_N 20004
#define CAP_V 100352

// Scratch (allocation-free rule: __device__ globals)
// preA/preB stored as packed bf16x2: 32 uint32 per row (64 cols)
__device__ uint32_t g_preA[(size_t)CAP_V * 32];
__device__ uint32_t g_preB[(size_t)CAP_N * 32];
__device__ float g_logits[CAP_E];

// lower half <- lo, upper half <- hi
__device__ __forceinline__ uint32_t pack_bf2(float lo, float hi) {
    uint32_t r;
    asm("cvt.rn.bf16x2.f32 %0, %1, %2;" : "=r"(r) : "f"(hi), "f"(lo));
    return r;
}
__device__ __forceinline__ uint32_t cvt2(float2 v) { return pack_bf2(v.x, v.y); }
// bf16x2: relu(a + b)
__device__ __forceinline__ uint32_t hadd_relu2(uint32_t a, uint32_t b) {
    __nv_bfloat162 av = *reinterpret_cast<__nv_bfloat162*>(&a);
    __nv_bfloat162 bv = *reinterpret_cast<__nv_bfloat162*>(&b);
    __nv_bfloat162 z = __float2bfloat162_rn(0.0f);
    __nv_bfloat162 r = __hmax2(__hadd2(av, bv), z);
    return *reinterpret_cast<uint32_t*>(&r);
}
__device__ __forceinline__ void mma_16816(float* c, uint32_t a0, uint32_t a1,
                                          uint32_t a2, uint32_t a3,
                                          uint32_t b0, uint32_t b1) {
    asm volatile(
        "mma.sync.aligned.m16n8k16.row.col.f32.bf16.bf16.f32 "
        "{%0,%1,%2,%3}, {%4,%5,%6,%7}, {%8,%9}, {%0,%1,%2,%3};"
        : "+f"(c[0]), "+f"(c[1]), "+f"(c[2]), "+f"(c[3])
        : "r"(a0), "r"(a1), "r"(a2), "r"(a3), "r"(b0), "r"(b1));
}

// ---------------------------------------------------------------------------
// Kernel 1 (HMMA): pre-compute
//   preA[v] = u2e[v] @ W1[0:64]  + b1   (v in [0,V))
//   preB[n] = u2e[nodes[n]] @ W1[64:128] (n in [0,N))
// B fragments pre-converted to bf16 and kept in SMEM (frees ~64 regs/thread
// for occupancy). Warp-tile: 16 rows x 64 cols, K=64 -> 32 mma.sync.
// ---------------------------------------------------------------------------
__global__ __launch_bounds__(256) void pre_mma_kernel(
    const int* __restrict__ nodes, const float* __restrict__ u2e,
    const float* __restrict__ w1, const float* __restrict__ b1,
    int V, int N)
{
    __shared__ float s_w1[8192];      // full W1 [128][64] fp32 stage (32 KB)
    __shared__ uint2 s_frag[2048];    // [half][kc][nc][lane] bf16 frags (16 KB)
    __shared__ float s_b1[64];

    const int tid  = threadIdx.x;
    const int lane = tid & 31;
    const int wid  = tid >> 5;
    const int g    = lane >> 2;
    const int tig  = lane & 3;

    const float4* w1v = (const float4*)w1;
    for (int i = tid; i < 2048; i += 256) ((float4*)s_w1)[i] = w1v[i];
    if (tid < 64) s_b1[tid] = b1[tid];
    __syncthreads();

    // Build bf16 fragment table for both W1 halves.
    for (int i = tid; i < 2048; i += 256) {
        int half = i >> 10;
        int rem  = i & 1023;
        int kc   = rem >> 8;
        int nc   = (rem >> 5) & 7;
        int ln   = rem & 31;
        int lg   = ln >> 2, lt = ln & 3;
        int k0 = kc * 16 + 2 * lt;
        int n  = nc * 8 + lg;
        const float* base = s_w1 + half * 4096;
        uint2 f;
        f.x = pack_bf2(base[k0 * 64 + n],       base[(k0 + 1) * 64 + n]);
        f.y = pack_bf2(base[(k0 + 8) * 64 + n], base[(k0 + 9) * 64 + n]);
        s_frag[i] = f;
    }
    __syncthreads();

    const int tA = (V + 15) / 16;
    const int tB = (N + 15) / 16;
    const int nw = gridDim.x * 8;
    const int w  = blockIdx.x * 8 + wid;
    int wA = (int)(((long long)nw * tA) / (tA + tB));
    if (wA < 1) wA = 1;
    if (wA > nw - 1) wA = nw - 1;

    const bool isA   = (w < wA);
    const int tiles  = isA ? tA : tB;
    const int tfirst = isA ? w : (w - wA);
    const int tstep  = isA ? wA : (nw - wA);
    const int rows   = isA ? V : N;
    uint32_t* gout   = isA ? g_preA : g_preB;
    const uint2* frag = s_frag + (isA ? 0 : 1024) + lane;

    for (int t = tfirst; t < tiles; t += tstep) {
        const int r0 = t * 16 + g;
        const int r1 = r0 + 8;
        const int rr0 = r0 < rows ? r0 : rows - 1;
        const int rr1 = r1 < rows ? r1 : rows - 1;
        const int src0 = isA ? rr0 : nodes[rr0];
        const int src1 = isA ? rr1 : nodes[rr1];
        const float2* x0 = (const float2*)(u2e + (size_t)src0 * 64);
        const float2* x1 = (const float2*)(u2e + (size_t)src1 * 64);

        float c[8][4];
        #pragma unroll
        for (int nc = 0; nc < 8; nc++) {
            c[nc][0] = 0.f; c[nc][1] = 0.f; c[nc][2] = 0.f; c[nc][3] = 0.f;
        }

        #pragma unroll
        for (int kc = 0; kc < 4; kc++) {
            const int i0 = kc * 8 + tig;
            const int i1 = i0 + 4;
            uint32_t a0 = cvt2(x0[i0]);
            uint32_t a1 = cvt2(x1[i0]);
            uint32_t a2 = cvt2(x0[i1]);
            uint32_t a3 = cvt2(x1[i1]);
            #pragma unroll
            for (int nc = 0; nc < 8; nc++) {
                uint2 b = frag[(kc * 8 + nc) * 32];
                mma_16816(c[nc], a0, a1, a2, a3, b.x, b.y);
            }
        }

        #pragma unroll
        for (int nc = 0; nc < 8; nc++) {
            const int col0 = nc * 8 + 2 * tig;
            const float add0 = isA ? s_b1[col0] : 0.0f;
            const float add1 = isA ? s_b1[col0 + 1] : 0.0f;
            uint32_t p0 = pack_bf2(c[nc][0] + add0, c[nc][1] + add1);
            uint32_t p1 = pack_bf2(c[nc][2] + add0, c[nc][3] + add1);
            if (r0 < rows) gout[(size_t)r0 * 32 + nc * 4 + tig] = p0;
            if (r1 < rows) gout[(size_t)r1 * 32 + nc * 4 + tig] = p1;
        }
    }
}

// ---------------------------------------------------------------------------
// Kernel 2 (HMMA): per warp-tile of 16 edges:
//   A[16,64] = relu(preA_bf[neigh] + preB_bf[seg])
//   H2 = A @ W2_bf16 ; logit[e] = b3 + sum_j relu(H2[e][j] + b2[j]) * w3[j]
// W2 fragments in SMEM.
// ---------------------------------------------------------------------------
__global__ __launch_bounds__(256) void edge_mma_kernel(
    const int* __restrict__ neigh, const int* __restrict__ seg,
    const float* __restrict__ w2, const float* __restrict__ b2,
    const float* __restrict__ w3, const float* __restrict__ b3,
    int E, int ntiles)
{
    __shared__ float s_w2[4096];      // 16 KB stage
    __shared__ uint2 s_frag[1024];    // 8 KB bf16 frags
    __shared__ float s_b2[64];
    __shared__ float s_w3[64];
    __shared__ float s_b3;

    const int tid  = threadIdx.x;
    const int lane = tid & 31;
    const int wid  = tid >> 5;
    const int g    = lane >> 2;
    const int tig  = lane & 3;

    const float4* w2v = (const float4*)w2;
    for (int i = tid; i < 1024; i += 256) ((float4*)s_w2)[i] = w2v[i];
    if (tid < 64) { s_b2[tid] = b2[tid]; s_w3[tid] = w3[tid]; }
    if (tid == 255) s_b3 = b3[0];
    __syncthreads();

    for (int i = tid; i < 1024; i += 256) {
        int kc = i >> 8;
        int nc = (i >> 5) & 7;
        int ln = i & 31;
        int lg = ln >> 2, lt = ln & 3;
        int k0 = kc * 16 + 2 * lt;
        int n  = nc * 8 + lg;
        uint2 f;
        f.x = pack_bf2(s_w2[k0 * 64 + n],       s_w2[(k0 + 1) * 64 + n]);
        f.y = pack_bf2(s_w2[(k0 + 8) * 64 + n], s_w2[(k0 + 9) * 64 + n]);
        s_frag[i] = f;
    }
    __syncthreads();

    const float vb3 = s_b3;
    const uint2* frag = s_frag + lane;
    const int warp_gid = blockIdx.x * 8 + wid;
    const int nwarps   = gridDim.x * 8;

    for (int tile = warp_gid; tile < ntiles; tile += nwarps) {
        const int base = tile * 16;
        const int e0 = base + g;
        const int e1 = e0 + 8;
        const int ee0 = e0 < E ? e0 : E - 1;
        const int ee1 = e1 < E ? e1 : E - 1;

        const uint32_t* pa0 = g_preA + (size_t)neigh[ee0] * 32;
        const uint32_t* pb0 = g_preB + (size_t)seg[ee0] * 32;
        const uint32_t* pa1 = g_preA + (size_t)neigh[ee1] * 32;
        const uint32_t* pb1 = g_preB + (size_t)seg[ee1] * 32;

        float c[8][4];
        #pragma unroll
        for (int nc = 0; nc < 8; nc++) {
            c[nc][0] = 0.f; c[nc][1] = 0.f; c[nc][2] = 0.f; c[nc][3] = 0.f;
        }

        #pragma unroll
        for (int kc = 0; kc < 4; kc++) {
            const int i0 = kc * 8 + tig;
            const int i1 = i0 + 4;
            uint32_t a0 = hadd_relu2(pa0[i0], pb0[i0]);
            uint32_t a1 = hadd_relu2(pa1[i0], pb1[i0]);
            uint32_t a2 = hadd_relu2(pa0[i1], pb0[i1]);
            uint32_t a3 = hadd_relu2(pa1[i1], pb1[i1]);

            #pragma unroll
            for (int nc = 0; nc < 8; nc++) {
                uint2 b = frag[(kc * 8 + nc) * 32];
                mma_16816(c[nc], a0, a1, a2, a3, b.x, b.y);
            }
        }

        float p0 = 0.f, p1 = 0.f;
        #pragma unroll
        for (int nc = 0; nc < 8; nc++) {
            const int col0 = nc * 8 + 2 * tig;
            const int col1 = col0 + 1;
            const float bb0 = s_b2[col0], bb1 = s_b2[col1];
            const float ww0 = s_w3[col0], ww1 = s_w3[col1];
            p0 = fmaf(fmaxf(c[nc][0] + bb0, 0.f), ww0, p0);
            p0 = fmaf(fmaxf(c[nc][1] + bb1, 0.f), ww1, p0);
            p1 = fmaf(fmaxf(c[nc][2] + bb0, 0.f), ww0, p1);
            p1 = fmaf(fmaxf(c[nc][3] + bb1, 0.f), ww1, p1);
        }
        p0 += __shfl_xor_sync(0xffffffffu, p0, 1);
        p0 += __shfl_xor_sync(0xffffffffu, p0, 2);
        p1 += __shfl_xor_sync(0xffffffffu, p1, 1);
        p1 += __shfl_xor_sync(0xffffffffu, p1, 2);

        if (tig == 0) {
            if (e0 < E) g_logits[e0] = p0 + vb3;
            if (e1 < E) g_logits[e1] = p1 + vb3;
        }
    }
}

// ---------------------------------------------------------------------------
// Kernel 3: warp-per-node segment softmax + attention-weighted sum.
// ex kept in registers (recomputed per 32-edge chunk, shfl-broadcast) — no
// g_ex global round-trip.
// ---------------------------------------------------------------------------
__global__ void agg_kernel(const int* __restrict__ neigh,
                           const int* __restrict__ seg,
                           const float* __restrict__ u2e,
                           float* __restrict__ out, int N, int E)
{
    int gw   = (blockIdx.x * blockDim.x + threadIdx.x) >> 5;
    int lane = threadIdx.x & 31;
    if (gw >= N) return;

    int bound = E;
    if (lane < 2) {
        int target = gw + lane;
        int lo = 0, hi = E;
        while (lo < hi) {
            int mid = (lo + hi) >> 1;
            if (seg[mid] < target) lo = mid + 1; else hi = mid;
        }
        bound = lo;
    }
    int s    = __shfl_sync(0xffffffffu, bound, 0);
    int epos = __shfl_sync(0xffffffffu, bound, 1);

    // pass 1: segment max
    float m = -INFINITY;
    for (int i = s + lane; i < epos; i += 32) m = fmaxf(m, g_logits[i]);
    #pragma unroll
    for (int o = 16; o; o >>= 1) m = fmaxf(m, __shfl_xor_sync(0xffffffffu, m, o));
    if (!isfinite(m)) m = 0.0f;

    // pass 2: segment sum of exp
    float sum = 0.0f;
    for (int i = s + lane; i < epos; i += 32) sum += __expf(g_logits[i] - m);
    #pragma unroll
    for (int o = 16; o; o >>= 1) sum += __shfl_xor_sync(0xffffffffu, sum, o);
    float inv = 1.0f / fmaxf(sum, 1e-9f);

    // pass 3: weighted gather-sum; att recomputed per chunk, shfl-broadcast
    float ax[4] = {0.f, 0.f, 0.f, 0.f};
    float ay[4] = {0.f, 0.f, 0.f, 0.f};
    for (int c0 = s; c0 < epos; c0 += 32) {
        int i = c0 + lane;
        float exk = (i < epos) ? __expf(g_logits[i] - m) * inv : 0.0f;
        int nval = epos - c0;
        if (nval > 32) nval = 32;
        int j = 0;
        for (; j + 3 < nval; j += 4) {
            float att[4];
            float2 v[4];
            #pragma unroll
            for (int u = 0; u < 4; u++) {
                att[u] = __shfl_sync(0xffffffffu, exk, j + u);
                v[u] = ((const float2*)(u2e + (size_t)neigh[c0 + j + u] * 64))[lane];
            }
            #pragma unroll
            for (int u = 0; u < 4; u++) {
                ax[u] = fmaf(att[u], v[u].x, ax[u]);
                ay[u] = fmaf(att[u], v[u].y, ay[u]);
            }
        }
        for (; j < nval; j++) {
            float att = __shfl_sync(0xffffffffu, exk, j);
            float2 v = ((const float2*)(u2e + (size_t)neigh[c0 + j] * 64))[lane];
            ax[0] = fmaf(att, v.x, ax[0]);
            ay[0] = fmaf(att, v.y, ay[0]);
        }
    }
    float ox = (ax[0] + ax[1]) + (ax[2] + ax[3]);
    float oy = (ay[0] + ay[1]) + (ay[2] + ay[3]);
    ((float2*)out)[(size_t)gw * 32 + lane] = make_float2(ox, oy);
}

// ---------------------------------------------------------------------------
extern "C" void kernel_launch(void* const* d_in, const int* in_sizes, int n_in,
                              void* d_out, int out_size)
{
    const int*   nodes = (const int*)d_in[0];
    const int*   neigh = (const int*)d_in[1];
    const int*   seg   = (const int*)d_in[2];
    const float* u2e   = (const float*)d_in[3];
    const float* w1    = (const float*)d_in[4];
    const float* b1    = (const float*)d_in[5];
    const float* w2    = (const float*)d_in[6];
    const float* b2    = (const float*)d_in[7];
    const float* w3    = (const float*)d_in[8];
    const float* b3    = (const float*)d_in[9];

    int N = in_sizes[0];
    int E = in_sizes[1];
    int V = in_sizes[3] / 64;
    if (E > CAP_E) E = CAP_E;
    if (N > CAP_N - 2) N = CAP_N - 2;
    if (V > CAP_V) V = CAP_V;

    int pre_tiles = (V + 15) / 16 + (N + 15) / 16;
    int pre_grid = (pre_tiles + 7) / 8;
    if (pre_grid > 296) pre_grid = 296;
    pre_mma_kernel<<<pre_grid, 256>>>(nodes, u2e, w1, b1, V, N);

    int ntiles = (E + 15) / 16;
    int grid = 296;
    int maxgrid = (ntiles + 7) / 8;
    if (grid > maxgrid) grid = maxgrid;
    edge_mma_kernel<<<grid, 256>>>(neigh, seg, w2, b2, w3, b3, E, ntiles);

    agg_kernel<<<(N * 32 + 255) / 256, 256>>>(neigh, seg, u2e, (float*)d_out, N, E);
}

// round 8
// speedup vs baseline: 1.0287x; 1.0287x over previous
#include <cuda_runtime.h>
#include <cuda_bf16.h>
#include <cstdint>
#include <math.h>

#define CAP_E 655360
#define CAP_N 20004
#define CAP_V 100352

// Scratch (allocation-free rule: __device__ globals)
// preA/preB stored as packed bf16x2: 32 uint32 per row (64 cols)
__device__ uint32_t g_preA[(size_t)CAP_V * 32];
__device__ uint32_t g_preB[(size_t)CAP_N * 32];
__device__ float g_logits[CAP_E];
__device__ float g_ex[CAP_E];

// lower half <- lo, upper half <- hi
__device__ __forceinline__ uint32_t pack_bf2(float lo, float hi) {
    uint32_t r;
    asm("cvt.rn.bf16x2.f32 %0, %1, %2;" : "=r"(r) : "f"(hi), "f"(lo));
    return r;
}
__device__ __forceinline__ uint32_t cvt2(float2 v) { return pack_bf2(v.x, v.y); }
// bf16x2: relu(a + b)
__device__ __forceinline__ uint32_t hadd_relu2(uint32_t a, uint32_t b) {
    __nv_bfloat162 av = *reinterpret_cast<__nv_bfloat162*>(&a);
    __nv_bfloat162 bv = *reinterpret_cast<__nv_bfloat162*>(&b);
    __nv_bfloat162 z = __float2bfloat162_rn(0.0f);
    __nv_bfloat162 r = __hmax2(__hadd2(av, bv), z);
    return *reinterpret_cast<uint32_t*>(&r);
}
__device__ __forceinline__ void mma_16816(float* c, uint32_t a0, uint32_t a1,
                                          uint32_t a2, uint32_t a3,
                                          uint32_t b0, uint32_t b1) {
    asm volatile(
        "mma.sync.aligned.m16n8k16.row.col.f32.bf16.bf16.f32 "
        "{%0,%1,%2,%3}, {%4,%5,%6,%7}, {%8,%9}, {%0,%1,%2,%3};"
        : "+f"(c[0]), "+f"(c[1]), "+f"(c[2]), "+f"(c[3])
        : "r"(a0), "r"(a1), "r"(a2), "r"(a3), "r"(b0), "r"(b1));
}

// ---------------------------------------------------------------------------
// Kernel 1 (HMMA): preA[v] = u2e[v]@W1a + b1 ; preB[n] = u2e[nodes[n]]@W1b
// B fragments bf16 in SMEM (regs=64 -> 4 CTAs/SM at grid 592).
// ---------------------------------------------------------------------------
__global__ __launch_bounds__(256) void pre_mma_kernel(
    const int* __restrict__ nodes, const float* __restrict__ u2e,
    const float* __restrict__ w1, const float* __restrict__ b1,
    int V, int N)
{
    __shared__ float s_w1[8192];      // full W1 [128][64] fp32 stage (32 KB)
    __shared__ uint2 s_frag[2048];    // [half][kc][nc][lane] bf16 frags (16 KB)
    __shared__ float s_b1[64];

    const int tid  = threadIdx.x;
    const int lane = tid & 31;
    const int wid  = tid >> 5;
    const int g    = lane >> 2;
    const int tig  = lane & 3;

    const float4* w1v = (const float4*)w1;
    for (int i = tid; i < 2048; i += 256) ((float4*)s_w1)[i] = w1v[i];
    if (tid < 64) s_b1[tid] = b1[tid];
    __syncthreads();

    // Build bf16 fragment table for both W1 halves.
    for (int i = tid; i < 2048; i += 256) {
        int half = i >> 10;
        int rem  = i & 1023;
        int kc   = rem >> 8;
        int nc   = (rem >> 5) & 7;
        int ln   = rem & 31;
        int lg   = ln >> 2, lt = ln & 3;
        int k0 = kc * 16 + 2 * lt;
        int n  = nc * 8 + lg;
        const float* base = s_w1 + half * 4096;
        uint2 f;
        f.x = pack_bf2(base[k0 * 64 + n],       base[(k0 + 1) * 64 + n]);
        f.y = pack_bf2(base[(k0 + 8) * 64 + n], base[(k0 + 9) * 64 + n]);
        s_frag[i] = f;
    }
    __syncthreads();

    const int tA = (V + 15) / 16;
    const int tB = (N + 15) / 16;
    const int nw = gridDim.x * 8;
    const int w  = blockIdx.x * 8 + wid;
    int wA = (int)(((long long)nw * tA) / (tA + tB));
    if (wA < 1) wA = 1;
    if (wA > nw - 1) wA = nw - 1;

    const bool isA   = (w < wA);
    const int tiles  = isA ? tA : tB;
    const int tfirst = isA ? w : (w - wA);
    const int tstep  = isA ? wA : (nw - wA);
    const int rows   = isA ? V : N;
    uint32_t* gout   = isA ? g_preA : g_preB;
    const uint2* frag = s_frag + (isA ? 0 : 1024) + lane;

    for (int t = tfirst; t < tiles; t += tstep) {
        const int r0 = t * 16 + g;
        const int r1 = r0 + 8;
        const int rr0 = r0 < rows ? r0 : rows - 1;
        const int rr1 = r1 < rows ? r1 : rows - 1;
        const int src0 = isA ? rr0 : nodes[rr0];
        const int src1 = isA ? rr1 : nodes[rr1];
        const float2* x0 = (const float2*)(u2e + (size_t)src0 * 64);
        const float2* x1 = (const float2*)(u2e + (size_t)src1 * 64);

        float c[8][4];
        #pragma unroll
        for (int nc = 0; nc < 8; nc++) {
            c[nc][0] = 0.f; c[nc][1] = 0.f; c[nc][2] = 0.f; c[nc][3] = 0.f;
        }

        #pragma unroll
        for (int kc = 0; kc < 4; kc++) {
            const int i0 = kc * 8 + tig;
            const int i1 = i0 + 4;
            uint32_t a0 = cvt2(x0[i0]);
            uint32_t a1 = cvt2(x1[i0]);
            uint32_t a2 = cvt2(x0[i1]);
            uint32_t a3 = cvt2(x1[i1]);
            #pragma unroll
            for (int nc = 0; nc < 8; nc++) {
                uint2 b = frag[(kc * 8 + nc) * 32];
                mma_16816(c[nc], a0, a1, a2, a3, b.x, b.y);
            }
        }

        #pragma unroll
        for (int nc = 0; nc < 8; nc++) {
            const int col0 = nc * 8 + 2 * tig;
            const float add0 = isA ? s_b1[col0] : 0.0f;
            const float add1 = isA ? s_b1[col0 + 1] : 0.0f;
            uint32_t p0 = pack_bf2(c[nc][0] + add0, c[nc][1] + add1);
            uint32_t p1 = pack_bf2(c[nc][2] + add0, c[nc][3] + add1);
            if (r0 < rows) gout[(size_t)r0 * 32 + nc * 4 + tig] = p0;
            if (r1 < rows) gout[(size_t)r1 * 32 + nc * 4 + tig] = p1;
        }
    }
}

// ---------------------------------------------------------------------------
// Kernel 2 (HMMA): A[16,64] = relu(preA_bf[neigh] + preB_bf[seg]);
// H2 = A @ W2_bf16 ; logit = b3 + sum_j relu(H2_j + b2_j)*w3_j
// W2 fragments bf16 in SMEM (regs=64 -> 4 CTAs/SM at grid 592).
// ---------------------------------------------------------------------------
__global__ __launch_bounds__(256) void edge_mma_kernel(
    const int* __restrict__ neigh, const int* __restrict__ seg,
    const float* __restrict__ w2, const float* __restrict__ b2,
    const float* __restrict__ w3, const float* __restrict__ b3,
    int E, int ntiles)
{
    __shared__ float s_w2[4096];      // 16 KB stage
    __shared__ uint2 s_frag[1024];    // 8 KB bf16 frags
    __shared__ float s_b2[64];
    __shared__ float s_w3[64];
    __shared__ float s_b3;

    const int tid  = threadIdx.x;
    const int lane = tid & 31;
    const int wid  = tid >> 5;
    const int g    = lane >> 2;
    const int tig  = lane & 3;

    const float4* w2v = (const float4*)w2;
    for (int i = tid; i < 1024; i += 256) ((float4*)s_w2)[i] = w2v[i];
    if (tid < 64) { s_b2[tid] = b2[tid]; s_w3[tid] = w3[tid]; }
    if (tid == 255) s_b3 = b3[0];
    __syncthreads();

    for (int i = tid; i < 1024; i += 256) {
        int kc = i >> 8;
        int nc = (i >> 5) & 7;
        int ln = i & 31;
        int lg = ln >> 2, lt = ln & 3;
        int k0 = kc * 16 + 2 * lt;
        int n  = nc * 8 + lg;
        uint2 f;
        f.x = pack_bf2(s_w2[k0 * 64 + n],       s_w2[(k0 + 1) * 64 + n]);
        f.y = pack_bf2(s_w2[(k0 + 8) * 64 + n], s_w2[(k0 + 9) * 64 + n]);
        s_frag[i] = f;
    }
    __syncthreads();

    const float vb3 = s_b3;
    const uint2* frag = s_frag + lane;
    const int warp_gid = blockIdx.x * 8 + wid;
    const int nwarps   = gridDim.x * 8;

    for (int tile = warp_gid; tile < ntiles; tile += nwarps) {
        const int base = tile * 16;
        const int e0 = base + g;
        const int e1 = e0 + 8;
        const int ee0 = e0 < E ? e0 : E - 1;
        const int ee1 = e1 < E ? e1 : E - 1;

        const uint32_t* pa0 = g_preA + (size_t)neigh[ee0] * 32;
        const uint32_t* pb0 = g_preB + (size_t)seg[ee0] * 32;
        const uint32_t* pa1 = g_preA + (size_t)neigh[ee1] * 32;
        const uint32_t* pb1 = g_preB + (size_t)seg[ee1] * 32;

        float c[8][4];
        #pragma unroll
        for (int nc = 0; nc < 8; nc++) {
            c[nc][0] = 0.f; c[nc][1] = 0.f; c[nc][2] = 0.f; c[nc][3] = 0.f;
        }

        #pragma unroll
        for (int kc = 0; kc < 4; kc++) {
            const int i0 = kc * 8 + tig;
            const int i1 = i0 + 4;
            uint32_t a0 = hadd_relu2(pa0[i0], pb0[i0]);
            uint32_t a1 = hadd_relu2(pa1[i0], pb1[i0]);
            uint32_t a2 = hadd_relu2(pa0[i1], pb0[i1]);
            uint32_t a3 = hadd_relu2(pa1[i1], pb1[i1]);

            #pragma unroll
            for (int nc = 0; nc < 8; nc++) {
                uint2 b = frag[(kc * 8 + nc) * 32];
                mma_16816(c[nc], a0, a1, a2, a3, b.x, b.y);
            }
        }

        float p0 = 0.f, p1 = 0.f;
        #pragma unroll
        for (int nc = 0; nc < 8; nc++) {
            const int col0 = nc * 8 + 2 * tig;
            const int col1 = col0 + 1;
            const float bb0 = s_b2[col0], bb1 = s_b2[col1];
            const float ww0 = s_w3[col0], ww1 = s_w3[col1];
            p0 = fmaf(fmaxf(c[nc][0] + bb0, 0.f), ww0, p0);
            p0 = fmaf(fmaxf(c[nc][1] + bb1, 0.f), ww1, p0);
            p1 = fmaf(fmaxf(c[nc][2] + bb0, 0.f), ww0, p1);
            p1 = fmaf(fmaxf(c[nc][3] + bb1, 0.f), ww1, p1);
        }
        p0 += __shfl_xor_sync(0xffffffffu, p0, 1);
        p0 += __shfl_xor_sync(0xffffffffu, p0, 2);
        p1 += __shfl_xor_sync(0xffffffffu, p1, 1);
        p1 += __shfl_xor_sync(0xffffffffu, p1, 2);

        if (tig == 0) {
            if (e0 < E) g_logits[e0] = p0 + vb3;
            if (e1 < E) g_logits[e1] = p1 + vb3;
        }
    }
}

// ---------------------------------------------------------------------------
// Kernel 3: warp-per-node segment softmax + attention-weighted sum (R6 form:
// g_ex round-trip, x4-unrolled gather).
// ---------------------------------------------------------------------------
__global__ void agg_kernel(const int* __restrict__ neigh,
                           const int* __restrict__ seg,
                           const float* __restrict__ u2e,
                           float* __restrict__ out, int N, int E)
{
    int gw   = (blockIdx.x * blockDim.x + threadIdx.x) >> 5;
    int lane = threadIdx.x & 31;
    if (gw >= N) return;

    int bound = E;
    if (lane < 2) {
        int target = gw + lane;
        int lo = 0, hi = E;
        while (lo < hi) {
            int mid = (lo + hi) >> 1;
            if (seg[mid] < target) lo = mid + 1; else hi = mid;
        }
        bound = lo;
    }
    int s    = __shfl_sync(0xffffffffu, bound, 0);
    int epos = __shfl_sync(0xffffffffu, bound, 1);

    float m = -INFINITY;
    for (int i = s + lane; i < epos; i += 32) m = fmaxf(m, g_logits[i]);
    #pragma unroll
    for (int o = 16; o; o >>= 1) m = fmaxf(m, __shfl_xor_sync(0xffffffffu, m, o));
    if (!isfinite(m)) m = 0.0f;

    float sum = 0.0f;
    for (int i = s + lane; i < epos; i += 32) {
        float ex = __expf(g_logits[i] - m);
        g_ex[i] = ex;
        sum += ex;
    }
    #pragma unroll
    for (int o = 16; o; o >>= 1) sum += __shfl_xor_sync(0xffffffffu, sum, o);
    float inv = 1.0f / fmaxf(sum, 1e-9f);
    __syncwarp();

    float ax[4] = {0.f, 0.f, 0.f, 0.f};
    float ay[4] = {0.f, 0.f, 0.f, 0.f};
    int i = s;
    for (; i + 3 < epos; i += 4) {
        float att[4];
        float2 v[4];
        #pragma unroll
        for (int u = 0; u < 4; u++) {
            att[u] = g_ex[i + u] * inv;
            v[u] = ((const float2*)(u2e + (size_t)neigh[i + u] * 64))[lane];
        }
        #pragma unroll
        for (int u = 0; u < 4; u++) {
            ax[u] = fmaf(att[u], v[u].x, ax[u]);
            ay[u] = fmaf(att[u], v[u].y, ay[u]);
        }
    }
    for (; i < epos; i++) {
        float att = g_ex[i] * inv;
        float2 v = ((const float2*)(u2e + (size_t)neigh[i] * 64))[lane];
        ax[0] = fmaf(att, v.x, ax[0]);
        ay[0] = fmaf(att, v.y, ay[0]);
    }
    float ox = (ax[0] + ax[1]) + (ax[2] + ax[3]);
    float oy = (ay[0] + ay[1]) + (ay[2] + ay[3]);
    ((float2*)out)[(size_t)gw * 32 + lane] = make_float2(ox, oy);
}

// ---------------------------------------------------------------------------
extern "C" void kernel_launch(void* const* d_in, const int* in_sizes, int n_in,
                              void* d_out, int out_size)
{
    const int*   nodes = (const int*)d_in[0];
    const int*   neigh = (const int*)d_in[1];
    const int*   seg   = (const int*)d_in[2];
    const float* u2e   = (const float*)d_in[3];
    const float* w1    = (const float*)d_in[4];
    const float* b1    = (const float*)d_in[5];
    const float* w2    = (const float*)d_in[6];
    const float* b2    = (const float*)d_in[7];
    const float* w3    = (const float*)d_in[8];
    const float* b3    = (const float*)d_in[9];

    int N = in_sizes[0];
    int E = in_sizes[1];
    int V = in_sizes[3] / 64;
    if (E > CAP_E) E = CAP_E;
    if (N > CAP_N - 2) N = CAP_N - 2;
    if (V > CAP_V) V = CAP_V;

    // 4 CTAs/SM target (148 SMs): grid 592
    int pre_tiles = (V + 15) / 16 + (N + 15) / 16;
    int pre_grid = (pre_tiles + 7) / 8;
    if (pre_grid > 592) pre_grid = 592;
    pre_mma_kernel<<<pre_grid, 256>>>(nodes, u2e, w1, b1, V, N);

    int ntiles = (E + 15) / 16;
    int grid = 592;
    int maxgrid = (ntiles + 7) / 8;
    if (grid > maxgrid) grid = maxgrid;
    edge_mma_kernel<<<grid, 256>>>(neigh, seg, w2, b2, w3, b3, E, ntiles);

    agg_kernel<<<(N * 32 + 255) / 256, 256>>>(neigh, seg, u2e, (float*)d_out, N, E);
}

// round 9
// speedup vs baseline: 1.2926x; 1.2565x over previous
#include <cuda_runtime.h>
#include <cuda_bf16.h>
#include <cstdint>
#include <math.h>

#define CAP_E 655360
#define CAP_N 20004
#define CAP_V 100352

// Scratch (allocation-free rule: __device__ globals)
__device__ uint32_t g_preA[(size_t)CAP_V * 32];   // bf16x2-packed rows
__device__ uint32_t g_preB[(size_t)CAP_N * 32];
__device__ float g_logits[CAP_E];
__device__ float g_ex[CAP_E];

// lower half <- lo, upper half <- hi
__device__ __forceinline__ uint32_t pack_bf2(float lo, float hi) {
    uint32_t r;
    asm("cvt.rn.bf16x2.f32 %0, %1, %2;" : "=r"(r) : "f"(hi), "f"(lo));
    return r;
}
// bf16x2: relu(a + b)
__device__ __forceinline__ uint32_t hadd_relu2(uint32_t a, uint32_t b) {
    __nv_bfloat162 av = *reinterpret_cast<__nv_bfloat162*>(&a);
    __nv_bfloat162 bv = *reinterpret_cast<__nv_bfloat162*>(&b);
    __nv_bfloat162 z = __float2bfloat162_rn(0.0f);
    __nv_bfloat162 r = __hmax2(__hadd2(av, bv), z);
    return *reinterpret_cast<uint32_t*>(&r);
}
__device__ __forceinline__ void mma_16816(float* c, uint32_t a0, uint32_t a1,
                                          uint32_t a2, uint32_t a3,
                                          uint32_t b0, uint32_t b1) {
    asm volatile(
        "mma.sync.aligned.m16n8k16.row.col.f32.bf16.bf16.f32 "
        "{%0,%1,%2,%3}, {%4,%5,%6,%7}, {%8,%9}, {%0,%1,%2,%3};"
        : "+f"(c[0]), "+f"(c[1]), "+f"(c[2]), "+f"(c[3])
        : "r"(a0), "r"(a1), "r"(a2), "r"(a3), "r"(b0), "r"(b1));
}

// k-permutation used everywhere below:
//   thread tig owns physical k-chunk [32*tig, 32*tig+31] of each 64-wide row
//   (as u32 pairs: u32[8*tig + 2*kc] -> logical a0, u32[8*tig + 2*kc + 1] -> a2)
//   so B fragments must use weight rows:
//     b0[kc,tig] = {W[16*tig+4*kc], W[16*tig+4*kc+1]}
//     b1[kc,tig] = {W[16*tig+4*kc+2], W[16*tig+4*kc+3]}
// The k-sum is order-invariant, so the GEMM result is unchanged.

// ---------------------------------------------------------------------------
// Kernel 1 (HMMA): preA[v] = u2e[v]@W1a + b1 ; preB[n] = u2e[nodes[n]]@W1b
// B fragments bf16 in SMEM; vectorized float4 row loads (k-permuted).
// ---------------------------------------------------------------------------
__global__ __launch_bounds__(256) void pre_mma_kernel(
    const int* __restrict__ nodes, const float* __restrict__ u2e,
    const float* __restrict__ w1, const float* __restrict__ b1,
    int V, int N)
{
    __shared__ float s_w1[8192];      // full W1 [128][64] fp32 stage (32 KB)
    __shared__ uint2 s_frag[2048];    // [half][kc][nc][lane] bf16 frags (16 KB)
    __shared__ float s_b1[64];

    const int tid  = threadIdx.x;
    const int lane = tid & 31;
    const int wid  = tid >> 5;
    const int g    = lane >> 2;
    const int tig  = lane & 3;

    const float4* w1v = (const float4*)w1;
    for (int i = tid; i < 2048; i += 256) ((float4*)s_w1)[i] = w1v[i];
    if (tid < 64) s_b1[tid] = b1[tid];
    __syncthreads();

    // bf16 fragment table for both W1 halves, with permuted k rows.
    for (int i = tid; i < 2048; i += 256) {
        int half = i >> 10;
        int rem  = i & 1023;
        int kc   = rem >> 8;
        int nc   = (rem >> 5) & 7;
        int ln   = rem & 31;
        int lg   = ln >> 2, lt = ln & 3;
        int k0 = 16 * lt + 4 * kc;
        int n  = nc * 8 + lg;
        const float* base = s_w1 + half * 4096;
        uint2 f;
        f.x = pack_bf2(base[k0 * 64 + n],       base[(k0 + 1) * 64 + n]);
        f.y = pack_bf2(base[(k0 + 2) * 64 + n], base[(k0 + 3) * 64 + n]);
        s_frag[i] = f;
    }
    __syncthreads();

    const int tA = (V + 15) / 16;
    const int tB = (N + 15) / 16;
    const int nw = gridDim.x * 8;
    const int w  = blockIdx.x * 8 + wid;
    int wA = (int)(((long long)nw * tA) / (tA + tB));
    if (wA < 1) wA = 1;
    if (wA > nw - 1) wA = nw - 1;

    const bool isA   = (w < wA);
    const int tiles  = isA ? tA : tB;
    const int tfirst = isA ? w : (w - wA);
    const int tstep  = isA ? wA : (nw - wA);
    const int rows   = isA ? V : N;
    uint32_t* gout   = isA ? g_preA : g_preB;
    const uint2* frag = s_frag + (isA ? 0 : 1024) + lane;

    for (int t = tfirst; t < tiles; t += tstep) {
        const int r0 = t * 16 + g;
        const int r1 = r0 + 8;
        const int rr0 = r0 < rows ? r0 : rows - 1;
        const int rr1 = r1 < rows ? r1 : rows - 1;
        const int src0 = isA ? rr0 : nodes[rr0];
        const int src1 = isA ? rr1 : nodes[rr1];
        // thread's contiguous 64B chunk (4x float4) of each row
        const float4* x0 = (const float4*)(u2e + (size_t)src0 * 64) + tig * 4;
        const float4* x1 = (const float4*)(u2e + (size_t)src1 * 64) + tig * 4;

        float4 F0[4], F1[4];
        #pragma unroll
        for (int q = 0; q < 4; q++) { F0[q] = x0[q]; F1[q] = x1[q]; }

        float c[8][4];
        #pragma unroll
        for (int nc = 0; nc < 8; nc++) {
            c[nc][0] = 0.f; c[nc][1] = 0.f; c[nc][2] = 0.f; c[nc][3] = 0.f;
        }

        #pragma unroll
        for (int kc = 0; kc < 4; kc++) {
            uint32_t a0 = pack_bf2(F0[kc].x, F0[kc].y);
            uint32_t a1 = pack_bf2(F1[kc].x, F1[kc].y);
            uint32_t a2 = pack_bf2(F0[kc].z, F0[kc].w);
            uint32_t a3 = pack_bf2(F1[kc].z, F1[kc].w);
            #pragma unroll
            for (int nc = 0; nc < 8; nc++) {
                uint2 b = frag[(kc * 8 + nc) * 32];
                mma_16816(c[nc], a0, a1, a2, a3, b.x, b.y);
            }
        }

        #pragma unroll
        for (int nc = 0; nc < 8; nc++) {
            const int col0 = nc * 8 + 2 * tig;
            const float add0 = isA ? s_b1[col0] : 0.0f;
            const float add1 = isA ? s_b1[col0 + 1] : 0.0f;
            uint32_t p0 = pack_bf2(c[nc][0] + add0, c[nc][1] + add1);
            uint32_t p1 = pack_bf2(c[nc][2] + add0, c[nc][3] + add1);
            if (r0 < rows) gout[(size_t)r0 * 32 + nc * 4 + tig] = p0;
            if (r1 < rows) gout[(size_t)r1 * 32 + nc * 4 + tig] = p1;
        }
    }
}

// ---------------------------------------------------------------------------
// Kernel 2 (HMMA): A[16,64] = relu(preA_bf[neigh] + preB_bf[seg]);
// H2 = A @ W2_bf16 ; logit = b3 + sum_j relu(H2_j + b2_j)*w3_j
// W2 fragments in registers (k-permuted); uint4 row loads.
// ---------------------------------------------------------------------------
__global__ __launch_bounds__(256, 2) void edge_mma_kernel(
    const int* __restrict__ neigh, const int* __restrict__ seg,
    const float* __restrict__ w2, const float* __restrict__ b2,
    const float* __restrict__ w3, const float* __restrict__ b3,
    int E, int ntiles)
{
    __shared__ float s_w2[4096];
    __shared__ float s_b2[64];
    __shared__ float s_w3[64];
    __shared__ float s_b3;

    const int tid  = threadIdx.x;
    const int lane = tid & 31;
    const int wid  = tid >> 5;
    const int g    = lane >> 2;
    const int tig  = lane & 3;

    const float4* w2v = (const float4*)w2;
    for (int i = tid; i < 1024; i += 256) ((float4*)s_w2)[i] = w2v[i];
    if (tid < 64) { s_b2[tid] = b2[tid]; s_w3[tid] = w3[tid]; }
    if (tid == 255) s_b3 = b3[0];
    __syncthreads();

    // Register B fragments from permuted W2 rows.
    uint32_t Bf[4][8][2];
    #pragma unroll
    for (int kc = 0; kc < 4; kc++) {
        int k0 = 16 * tig + 4 * kc;
        #pragma unroll
        for (int nc = 0; nc < 8; nc++) {
            int n = nc * 8 + g;
            Bf[kc][nc][0] = pack_bf2(s_w2[k0 * 64 + n],       s_w2[(k0 + 1) * 64 + n]);
            Bf[kc][nc][1] = pack_bf2(s_w2[(k0 + 2) * 64 + n], s_w2[(k0 + 3) * 64 + n]);
        }
    }
    const float vb3 = s_b3;

    const int warp_gid = blockIdx.x * 8 + wid;
    const int nwarps   = gridDim.x * 8;

    for (int tile = warp_gid; tile < ntiles; tile += nwarps) {
        const int base = tile * 16;
        const int e0 = base + g;
        const int e1 = e0 + 8;
        const int ee0 = e0 < E ? e0 : E - 1;
        const int ee1 = e1 < E ? e1 : E - 1;

        // thread's contiguous 32B (2x uint4) chunk of each 128B row
        const uint4* qa0 = (const uint4*)(g_preA + (size_t)neigh[ee0] * 32) + tig * 2;
        const uint4* qb0 = (const uint4*)(g_preB + (size_t)seg[ee0]  * 32) + tig * 2;
        const uint4* qa1 = (const uint4*)(g_preA + (size_t)neigh[ee1] * 32) + tig * 2;
        const uint4* qb1 = (const uint4*)(g_preB + (size_t)seg[ee1]  * 32) + tig * 2;

        uint4 Aa0 = qa0[0], Ab0 = qa0[1];
        uint4 Ba0 = qb0[0], Bb0 = qb0[1];
        uint4 Aa1 = qa1[0], Ab1 = qa1[1];
        uint4 Ba1 = qb1[0], Bb1 = qb1[1];

        uint32_t r0[8], r1[8];
        r0[0] = hadd_relu2(Aa0.x, Ba0.x); r0[1] = hadd_relu2(Aa0.y, Ba0.y);
        r0[2] = hadd_relu2(Aa0.z, Ba0.z); r0[3] = hadd_relu2(Aa0.w, Ba0.w);
        r0[4] = hadd_relu2(Ab0.x, Bb0.x); r0[5] = hadd_relu2(Ab0.y, Bb0.y);
        r0[6] = hadd_relu2(Ab0.z, Bb0.z); r0[7] = hadd_relu2(Ab0.w, Bb0.w);
        r1[0] = hadd_relu2(Aa1.x, Ba1.x); r1[1] = hadd_relu2(Aa1.y, Ba1.y);
        r1[2] = hadd_relu2(Aa1.z, Ba1.z); r1[3] = hadd_relu2(Aa1.w, Ba1.w);
        r1[4] = hadd_relu2(Ab1.x, Bb1.x); r1[5] = hadd_relu2(Ab1.y, Bb1.y);
        r1[6] = hadd_relu2(Ab1.z, Bb1.z); r1[7] = hadd_relu2(Ab1.w, Bb1.w);

        float c[8][4];
        #pragma unroll
        for (int nc = 0; nc < 8; nc++) {
            c[nc][0] = 0.f; c[nc][1] = 0.f; c[nc][2] = 0.f; c[nc][3] = 0.f;
        }

        #pragma unroll
        for (int kc = 0; kc < 4; kc++) {
            uint32_t a0 = r0[2 * kc],     a2 = r0[2 * kc + 1];
            uint32_t a1 = r1[2 * kc],     a3 = r1[2 * kc + 1];
            #pragma unroll
            for (int nc = 0; nc < 8; nc++)
                mma_16816(c[nc], a0, a1, a2, a3, Bf[kc][nc][0], Bf[kc][nc][1]);
        }

        float p0 = 0.f, p1 = 0.f;
        #pragma unroll
        for (int nc = 0; nc < 8; nc++) {
            const int col0 = nc * 8 + 2 * tig;
            const int col1 = col0 + 1;
            const float bb0 = s_b2[col0], bb1 = s_b2[col1];
            const float ww0 = s_w3[col0], ww1 = s_w3[col1];
            p0 = fmaf(fmaxf(c[nc][0] + bb0, 0.f), ww0, p0);
            p0 = fmaf(fmaxf(c[nc][1] + bb1, 0.f), ww1, p0);
            p1 = fmaf(fmaxf(c[nc][2] + bb0, 0.f), ww0, p1);
            p1 = fmaf(fmaxf(c[nc][3] + bb1, 0.f), ww1, p1);
        }
        p0 += __shfl_xor_sync(0xffffffffu, p0, 1);
        p0 += __shfl_xor_sync(0xffffffffu, p0, 2);
        p1 += __shfl_xor_sync(0xffffffffu, p1, 1);
        p1 += __shfl_xor_sync(0xffffffffu, p1, 2);

        if (tig == 0) {
            if (e0 < E) g_logits[e0] = p0 + vb3;
            if (e1 < E) g_logits[e1] = p1 + vb3;
        }
    }
}

// ---------------------------------------------------------------------------
// Kernel 3: warp-per-node segment softmax + attention-weighted sum (R6 form).
// ---------------------------------------------------------------------------
__global__ void agg_kernel(const int* __restrict__ neigh,
                           const int* __restrict__ seg,
                           const float* __restrict__ u2e,
                           float* __restrict__ out, int N, int E)
{
    int gw   = (blockIdx.x * blockDim.x + threadIdx.x) >> 5;
    int lane = threadIdx.x & 31;
    if (gw >= N) return;

    int bound = E;
    if (lane < 2) {
        int target = gw + lane;
        int lo = 0, hi = E;
        while (lo < hi) {
            int mid = (lo + hi) >> 1;
            if (seg[mid] < target) lo = mid + 1; else hi = mid;
        }
        bound = lo;
    }
    int s    = __shfl_sync(0xffffffffu, bound, 0);
    int epos = __shfl_sync(0xffffffffu, bound, 1);

    float m = -INFINITY;
    for (int i = s + lane; i < epos; i += 32) m = fmaxf(m, g_logits[i]);
    #pragma unroll
    for (int o = 16; o; o >>= 1) m = fmaxf(m, __shfl_xor_sync(0xffffffffu, m, o));
    if (!isfinite(m)) m = 0.0f;

    float sum = 0.0f;
    for (int i = s + lane; i < epos; i += 32) {
        float ex = __expf(g_logits[i] - m);
        g_ex[i] = ex;
        sum += ex;
    }
    #pragma unroll
    for (int o = 16; o; o >>= 1) sum += __shfl_xor_sync(0xffffffffu, sum, o);
    float inv = 1.0f / fmaxf(sum, 1e-9f);
    __syncwarp();

    float ax[4] = {0.f, 0.f, 0.f, 0.f};
    float ay[4] = {0.f, 0.f, 0.f, 0.f};
    int i = s;
    for (; i + 3 < epos; i += 4) {
        float att[4];
        float2 v[4];
        #pragma unroll
        for (int u = 0; u < 4; u++) {
            att[u] = g_ex[i + u] * inv;
            v[u] = ((const float2*)(u2e + (size_t)neigh[i + u] * 64))[lane];
        }
        #pragma unroll
        for (int u = 0; u < 4; u++) {
            ax[u] = fmaf(att[u], v[u].x, ax[u]);
            ay[u] = fmaf(att[u], v[u].y, ay[u]);
        }
    }
    for (; i < epos; i++) {
        float att = g_ex[i] * inv;
        float2 v = ((const float2*)(u2e + (size_t)neigh[i] * 64))[lane];
        ax[0] = fmaf(att, v.x, ax[0]);
        ay[0] = fmaf(att, v.y, ay[0]);
    }
    float ox = (ax[0] + ax[1]) + (ax[2] + ax[3]);
    float oy = (ay[0] + ay[1]) + (ay[2] + ay[3]);
    ((float2*)out)[(size_t)gw * 32 + lane] = make_float2(ox, oy);
}

// ---------------------------------------------------------------------------
extern "C" void kernel_launch(void* const* d_in, const int* in_sizes, int n_in,
                              void* d_out, int out_size)
{
    const int*   nodes = (const int*)d_in[0];
    const int*   neigh = (const int*)d_in[1];
    const int*   seg   = (const int*)d_in[2];
    const float* u2e   = (const float*)d_in[3];
    const float* w1    = (const float*)d_in[4];
    const float* b1    = (const float*)d_in[5];
    const float* w2    = (const float*)d_in[6];
    const float* b2    = (const float*)d_in[7];
    const float* w3    = (const float*)d_in[8];
    const float* b3    = (const float*)d_in[9];

    int N = in_sizes[0];
    int E = in_sizes[1];
    int V = in_sizes[3] / 64;
    if (E > CAP_E) E = CAP_E;
    if (N > CAP_N - 2) N = CAP_N - 2;
    if (V > CAP_V) V = CAP_V;

    int pre_tiles = (V + 15) / 16 + (N + 15) / 16;
    int pre_grid = (pre_tiles + 7) / 8;
    if (pre_grid > 296) pre_grid = 296;
    pre_mma_kernel<<<pre_grid, 256>>>(nodes, u2e, w1, b1, V, N);

    int ntiles = (E + 15) / 16;
    int grid = 296;
    int maxgrid = (ntiles + 7) / 8;
    if (grid > maxgrid) grid = maxgrid;
    edge_mma_kernel<<<grid, 256>>>(neigh, seg, w2, b2, w3, b3, E, ntiles);

    agg_kernel<<<(N * 32 + 255) / 256, 256>>>(neigh, seg, u2e, (float*)d_out, N, E);
}

// round 10
// speedup vs baseline: 1.3265x; 1.0262x over previous
#include <cuda_runtime.h>
#include <cuda_bf16.h>
#include <cstdint>
#include <math.h>

#define CAP_E 655360
#define CAP_N 20004
#define CAP_V 100352

// Scratch (allocation-free rule: __device__ globals)
// preA/preB rows: 32 u32 of bf16x2, stored in PERMUTED pair order:
//   storage index s = tig*8 + nc   holds logical col-pair l = nc*4 + tig
// so a consumer reading contiguous chunk u32[8*tig .. 8*tig+7] gets logical
// pairs {4j + tig}, matching the standard m16n8k16 A-fragment layout.
__device__ uint32_t g_preA[(size_t)CAP_V * 32];
__device__ uint32_t g_preB[(size_t)CAP_N * 32];
__device__ float g_logits[CAP_E];
__device__ float g_ex[CAP_E];

// lower half <- lo, upper half <- hi
__device__ __forceinline__ uint32_t pack_bf2(float lo, float hi) {
    uint32_t r;
    asm("cvt.rn.bf16x2.f32 %0, %1, %2;" : "=r"(r) : "f"(hi), "f"(lo));
    return r;
}
// bf16x2: relu(a + b)
__device__ __forceinline__ uint32_t hadd_relu2(uint32_t a, uint32_t b) {
    __nv_bfloat162 av = *reinterpret_cast<__nv_bfloat162*>(&a);
    __nv_bfloat162 bv = *reinterpret_cast<__nv_bfloat162*>(&b);
    __nv_bfloat162 z = __float2bfloat162_rn(0.0f);
    __nv_bfloat162 r = __hmax2(__hadd2(av, bv), z);
    return *reinterpret_cast<uint32_t*>(&r);
}
__device__ __forceinline__ void mma_16816(float* c, uint32_t a0, uint32_t a1,
                                          uint32_t a2, uint32_t a3,
                                          uint32_t b0, uint32_t b1) {
    asm volatile(
        "mma.sync.aligned.m16n8k16.row.col.f32.bf16.bf16.f32 "
        "{%0,%1,%2,%3}, {%4,%5,%6,%7}, {%8,%9}, {%0,%1,%2,%3};"
        : "+f"(c[0]), "+f"(c[1]), "+f"(c[2]), "+f"(c[3])
        : "r"(a0), "r"(a1), "r"(a2), "r"(a3), "r"(b0), "r"(b1));
}

// ---------------------------------------------------------------------------
// Kernel 1 (HMMA): preA[v] = u2e[v]@W1a + b1 ; preB[n] = u2e[nodes[n]]@W1b
// Input k-permuted (thread owns contiguous 64B of u2e row -> frag rows
// k0 = 16*tig + 4*kc). Output stored in permuted pair order (2x STG.128/row).
// ---------------------------------------------------------------------------
__global__ __launch_bounds__(256) void pre_mma_kernel(
    const int* __restrict__ nodes, const float* __restrict__ u2e,
    const float* __restrict__ w1, const float* __restrict__ b1,
    int V, int N)
{
    __shared__ float s_w1[8192];      // full W1 [128][64] fp32 stage (32 KB)
    __shared__ uint2 s_frag[2048];    // [half][kc][nc][lane] bf16 frags (16 KB)
    __shared__ float s_b1[64];

    const int tid  = threadIdx.x;
    const int lane = tid & 31;
    const int wid  = tid >> 5;
    const int g    = lane >> 2;
    const int tig  = lane & 3;

    const float4* w1v = (const float4*)w1;
    for (int i = tid; i < 2048; i += 256) ((float4*)s_w1)[i] = w1v[i];
    if (tid < 64) s_b1[tid] = b1[tid];
    __syncthreads();

    // bf16 fragment table for both W1 halves, with permuted k rows.
    for (int i = tid; i < 2048; i += 256) {
        int half = i >> 10;
        int rem  = i & 1023;
        int kc   = rem >> 8;
        int nc   = (rem >> 5) & 7;
        int ln   = rem & 31;
        int lg   = ln >> 2, lt = ln & 3;
        int k0 = 16 * lt + 4 * kc;
        int n  = nc * 8 + lg;
        const float* base = s_w1 + half * 4096;
        uint2 f;
        f.x = pack_bf2(base[k0 * 64 + n],       base[(k0 + 1) * 64 + n]);
        f.y = pack_bf2(base[(k0 + 2) * 64 + n], base[(k0 + 3) * 64 + n]);
        s_frag[i] = f;
    }
    __syncthreads();

    const int tA = (V + 15) / 16;
    const int tB = (N + 15) / 16;
    const int nw = gridDim.x * 8;
    const int w  = blockIdx.x * 8 + wid;
    int wA = (int)(((long long)nw * tA) / (tA + tB));
    if (wA < 1) wA = 1;
    if (wA > nw - 1) wA = nw - 1;

    const bool isA   = (w < wA);
    const int tiles  = isA ? tA : tB;
    const int tfirst = isA ? w : (w - wA);
    const int tstep  = isA ? wA : (nw - wA);
    const int rows   = isA ? V : N;
    uint32_t* gout   = isA ? g_preA : g_preB;
    const uint2* frag = s_frag + (isA ? 0 : 1024) + lane;

    for (int t = tfirst; t < tiles; t += tstep) {
        const int r0 = t * 16 + g;
        const int r1 = r0 + 8;
        const int rr0 = r0 < rows ? r0 : rows - 1;
        const int rr1 = r1 < rows ? r1 : rows - 1;
        const int src0 = isA ? rr0 : nodes[rr0];
        const int src1 = isA ? rr1 : nodes[rr1];
        // thread's contiguous 64B chunk (4x float4) of each row
        const float4* x0 = (const float4*)(u2e + (size_t)src0 * 64) + tig * 4;
        const float4* x1 = (const float4*)(u2e + (size_t)src1 * 64) + tig * 4;

        float4 F0[4], F1[4];
        #pragma unroll
        for (int q = 0; q < 4; q++) { F0[q] = x0[q]; F1[q] = x1[q]; }

        float c[8][4];
        #pragma unroll
        for (int nc = 0; nc < 8; nc++) {
            c[nc][0] = 0.f; c[nc][1] = 0.f; c[nc][2] = 0.f; c[nc][3] = 0.f;
        }

        #pragma unroll
        for (int kc = 0; kc < 4; kc++) {
            uint32_t a0 = pack_bf2(F0[kc].x, F0[kc].y);
            uint32_t a1 = pack_bf2(F1[kc].x, F1[kc].y);
            uint32_t a2 = pack_bf2(F0[kc].z, F0[kc].w);
            uint32_t a3 = pack_bf2(F1[kc].z, F1[kc].w);
            #pragma unroll
            for (int nc = 0; nc < 8; nc++) {
                uint2 b = frag[(kc * 8 + nc) * 32];
                mma_16816(c[nc], a0, a1, a2, a3, b.x, b.y);
            }
        }

        // Permuted-pair epilogue: thread's 8 u32 per row are contiguous.
        uint32_t o0[8], o1[8];
        #pragma unroll
        for (int nc = 0; nc < 8; nc++) {
            const int col0 = nc * 8 + 2 * tig;
            const float add0 = isA ? s_b1[col0] : 0.0f;
            const float add1 = isA ? s_b1[col0 + 1] : 0.0f;
            o0[nc] = pack_bf2(c[nc][0] + add0, c[nc][1] + add1);
            o1[nc] = pack_bf2(c[nc][2] + add0, c[nc][3] + add1);
        }
        if (r0 < rows) {
            uint4* p = (uint4*)(gout + (size_t)r0 * 32 + tig * 8);
            p[0] = ((uint4*)o0)[0]; p[1] = ((uint4*)o0)[1];
        }
        if (r1 < rows) {
            uint4* p = (uint4*)(gout + (size_t)r1 * 32 + tig * 8);
            p[0] = ((uint4*)o1)[0]; p[1] = ((uint4*)o1)[1];
        }
    }
}

// ---------------------------------------------------------------------------
// Kernel 2 (HMMA): A[16,64] = relu(preA_bf[neigh] + preB_bf[seg]);
// H2 = A @ W2_bf16 ; logit = b3 + sum_j relu(H2_j + b2_j)*w3_j
// Contiguous 32B chunk loads; STANDARD B-frag layout (matches the permuted
// pair storage written by pre_mma_kernel).
// ---------------------------------------------------------------------------
__global__ __launch_bounds__(256, 2) void edge_mma_kernel(
    const int* __restrict__ neigh, const int* __restrict__ seg,
    const float* __restrict__ w2, const float* __restrict__ b2,
    const float* __restrict__ w3, const float* __restrict__ b3,
    int E, int ntiles)
{
    __shared__ float s_w2[4096];
    __shared__ float s_b2[64];
    __shared__ float s_w3[64];
    __shared__ float s_b3;

    const int tid  = threadIdx.x;
    const int lane = tid & 31;
    const int wid  = tid >> 5;
    const int g    = lane >> 2;
    const int tig  = lane & 3;

    const float4* w2v = (const float4*)w2;
    for (int i = tid; i < 1024; i += 256) ((float4*)s_w2)[i] = w2v[i];
    if (tid < 64) { s_b2[tid] = b2[tid]; s_w3[tid] = w3[tid]; }
    if (tid == 255) s_b3 = b3[0];
    __syncthreads();

    // Standard m16n8k16 B fragments (logical k order).
    uint32_t Bf[4][8][2];
    #pragma unroll
    for (int kc = 0; kc < 4; kc++) {
        int k0 = kc * 16 + 2 * tig;
        #pragma unroll
        for (int nc = 0; nc < 8; nc++) {
            int n = nc * 8 + g;
            Bf[kc][nc][0] = pack_bf2(s_w2[k0 * 64 + n],       s_w2[(k0 + 1) * 64 + n]);
            Bf[kc][nc][1] = pack_bf2(s_w2[(k0 + 8) * 64 + n], s_w2[(k0 + 9) * 64 + n]);
        }
    }
    const float vb3 = s_b3;

    const int warp_gid = blockIdx.x * 8 + wid;
    const int nwarps   = gridDim.x * 8;

    for (int tile = warp_gid; tile < ntiles; tile += nwarps) {
        const int base = tile * 16;
        const int e0 = base + g;
        const int e1 = e0 + 8;
        const int ee0 = e0 < E ? e0 : E - 1;
        const int ee1 = e1 < E ? e1 : E - 1;

        // thread's contiguous 32B (2x uint4) chunk of each 128B row
        const uint4* qa0 = (const uint4*)(g_preA + (size_t)neigh[ee0] * 32) + tig * 2;
        const uint4* qb0 = (const uint4*)(g_preB + (size_t)seg[ee0]  * 32) + tig * 2;
        const uint4* qa1 = (const uint4*)(g_preA + (size_t)neigh[ee1] * 32) + tig * 2;
        const uint4* qb1 = (const uint4*)(g_preB + (size_t)seg[ee1]  * 32) + tig * 2;

        uint4 Aa0 = qa0[0], Ab0 = qa0[1];
        uint4 Ba0 = qb0[0], Bb0 = qb0[1];
        uint4 Aa1 = qa1[0], Ab1 = qa1[1];
        uint4 Ba1 = qb1[0], Bb1 = qb1[1];

        uint32_t r0[8], r1[8];
        r0[0] = hadd_relu2(Aa0.x, Ba0.x); r0[1] = hadd_relu2(Aa0.y, Ba0.y);
        r0[2] = hadd_relu2(Aa0.z, Ba0.z); r0[3] = hadd_relu2(Aa0.w, Ba0.w);
        r0[4] = hadd_relu2(Ab0.x, Bb0.x); r0[5] = hadd_relu2(Ab0.y, Bb0.y);
        r0[6] = hadd_relu2(Ab0.z, Bb0.z); r0[7] = hadd_relu2(Ab0.w, Bb0.w);
        r1[0] = hadd_relu2(Aa1.x, Ba1.x); r1[1] = hadd_relu2(Aa1.y, Ba1.y);
        r1[2] = hadd_relu2(Aa1.z, Ba1.z); r1[3] = hadd_relu2(Aa1.w, Ba1.w);
        r1[4] = hadd_relu2(Ab1.x, Bb1.x); r1[5] = hadd_relu2(Ab1.y, Bb1.y);
        r1[6] = hadd_relu2(Ab1.z, Bb1.z); r1[7] = hadd_relu2(Ab1.w, Bb1.w);

        float c[8][4];
        #pragma unroll
        for (int nc = 0; nc < 8; nc++) {
            c[nc][0] = 0.f; c[nc][1] = 0.f; c[nc][2] = 0.f; c[nc][3] = 0.f;
        }

        // storage offset j=2kc -> logical pair 8kc+tig (a0);
        // j=2kc+1 -> logical pair 8kc+4+tig (a2): standard fragment rows.
        #pragma unroll
        for (int kc = 0; kc < 4; kc++) {
            uint32_t a0 = r0[2 * kc],     a2 = r0[2 * kc + 1];
            uint32_t a1 = r1[2 * kc],     a3 = r1[2 * kc + 1];
            #pragma unroll
            for (int nc = 0; nc < 8; nc++)
                mma_16816(c[nc], a0, a1, a2, a3, Bf[kc][nc][0], Bf[kc][nc][1]);
        }

        float p0 = 0.f, p1 = 0.f;
        #pragma unroll
        for (int nc = 0; nc < 8; nc++) {
            const int col0 = nc * 8 + 2 * tig;
            const int col1 = col0 + 1;
            const float bb0 = s_b2[col0], bb1 = s_b2[col1];
            const float ww0 = s_w3[col0], ww1 = s_w3[col1];
            p0 = fmaf(fmaxf(c[nc][0] + bb0, 0.f), ww0, p0);
            p0 = fmaf(fmaxf(c[nc][1] + bb1, 0.f), ww1, p0);
            p1 = fmaf(fmaxf(c[nc][2] + bb0, 0.f), ww0, p1);
            p1 = fmaf(fmaxf(c[nc][3] + bb1, 0.f), ww1, p1);
        }
        p0 += __shfl_xor_sync(0xffffffffu, p0, 1);
        p0 += __shfl_xor_sync(0xffffffffu, p0, 2);
        p1 += __shfl_xor_sync(0xffffffffu, p1, 1);
        p1 += __shfl_xor_sync(0xffffffffu, p1, 2);

        if (tig == 0) {
            if (e0 < E) g_logits[e0] = p0 + vb3;
            if (e1 < E) g_logits[e1] = p1 + vb3;
        }
    }
}

// ---------------------------------------------------------------------------
// Kernel 3: warp-per-node segment softmax + attention-weighted sum.
// Pass 3: lanes 0-15 own even edges, 16-31 odd; each lane loads one float4
// of the row (16 LDG.128 per edge-row instead of 32 LDG.64), x2 unrolled.
// ---------------------------------------------------------------------------
__global__ void agg_kernel(const int* __restrict__ neigh,
                           const int* __restrict__ seg,
                           const float* __restrict__ u2e,
                           float* __restrict__ out, int N, int E)
{
    int gw   = (blockIdx.x * blockDim.x + threadIdx.x) >> 5;
    int lane = threadIdx.x & 31;
    if (gw >= N) return;

    int bound = E;
    if (lane < 2) {
        int target = gw + lane;
        int lo = 0, hi = E;
        while (lo < hi) {
            int mid = (lo + hi) >> 1;
            if (seg[mid] < target) lo = mid + 1; else hi = mid;
        }
        bound = lo;
    }
    int s    = __shfl_sync(0xffffffffu, bound, 0);
    int epos = __shfl_sync(0xffffffffu, bound, 1);

    float m = -INFINITY;
    for (int i = s + lane; i < epos; i += 32) m = fmaxf(m, g_logits[i]);
    #pragma unroll
    for (int o = 16; o; o >>= 1) m = fmaxf(m, __shfl_xor_sync(0xffffffffu, m, o));
    if (!isfinite(m)) m = 0.0f;

    float sum = 0.0f;
    for (int i = s + lane; i < epos; i += 32) {
        float ex = __expf(g_logits[i] - m);
        g_ex[i] = ex;
        sum += ex;
    }
    #pragma unroll
    for (int o = 16; o; o >>= 1) sum += __shfl_xor_sync(0xffffffffu, sum, o);
    float inv = 1.0f / fmaxf(sum, 1e-9f);
    __syncwarp();

    // pass 3: half-warp per edge, float4 per lane, x2 unroll
    const int half = lane >> 4;     // 0 = even edges, 1 = odd edges
    const int qc   = lane & 15;     // float4 index within 256B row
    float4 acc0 = make_float4(0.f, 0.f, 0.f, 0.f);
    float4 acc1 = make_float4(0.f, 0.f, 0.f, 0.f);
    int i = s + half;
    for (; i + 2 < epos; i += 4) {
        float att0 = g_ex[i] * inv;
        float att1 = g_ex[i + 2] * inv;
        float4 v0 = ((const float4*)(u2e + (size_t)neigh[i] * 64))[qc];
        float4 v1 = ((const float4*)(u2e + (size_t)neigh[i + 2] * 64))[qc];
        acc0.x = fmaf(att0, v0.x, acc0.x);
        acc0.y = fmaf(att0, v0.y, acc0.y);
        acc0.z = fmaf(att0, v0.z, acc0.z);
        acc0.w = fmaf(att0, v0.w, acc0.w);
        acc1.x = fmaf(att1, v1.x, acc1.x);
        acc1.y = fmaf(att1, v1.y, acc1.y);
        acc1.z = fmaf(att1, v1.z, acc1.z);
        acc1.w = fmaf(att1, v1.w, acc1.w);
    }
    if (i < epos) {
        float att = g_ex[i] * inv;
        float4 v = ((const float4*)(u2e + (size_t)neigh[i] * 64))[qc];
        acc0.x = fmaf(att, v.x, acc0.x);
        acc0.y = fmaf(att, v.y, acc0.y);
        acc0.z = fmaf(att, v.z, acc0.z);
        acc0.w = fmaf(att, v.w, acc0.w);
    }
    acc0.x += acc1.x; acc0.y += acc1.y; acc0.z += acc1.z; acc0.w += acc1.w;
    // combine even/odd halves (partner lane = lane ^ 16)
    acc0.x += __shfl_xor_sync(0xffffffffu, acc0.x, 16);
    acc0.y += __shfl_xor_sync(0xffffffffu, acc0.y, 16);
    acc0.z += __shfl_xor_sync(0xffffffffu, acc0.z, 16);
    acc0.w += __shfl_xor_sync(0xffffffffu, acc0.w, 16);
    if (lane < 16)
        ((float4*)out)[(size_t)gw * 16 + qc] = acc0;
}

// ---------------------------------------------------------------------------
extern "C" void kernel_launch(void* const* d_in, const int* in_sizes, int n_in,
                              void* d_out, int out_size)
{
    const int*   nodes = (const int*)d_in[0];
    const int*   neigh = (const int*)d_in[1];
    const int*   seg   = (const int*)d_in[2];
    const float* u2e   = (const float*)d_in[3];
    const float* w1    = (const float*)d_in[4];
    const float* b1    = (const float*)d_in[5];
    const float* w2    = (const float*)d_in[6];
    const float* b2    = (const float*)d_in[7];
    const float* w3    = (const float*)d_in[8];
    const float* b3    = (const float*)d_in[9];

    int N = in_sizes[0];
    int E = in_sizes[1];
    int V = in_sizes[3] / 64;
    if (E > CAP_E) E = CAP_E;
    if (N > CAP_N - 2) N = CAP_N - 2;
    if (V > CAP_V) V = CAP_V;

    int pre_tiles = (V + 15) / 16 + (N + 15) / 16;
    int pre_grid = (pre_tiles + 7) / 8;
    if (pre_grid > 296) pre_grid = 296;
    pre_mma_kernel<<<pre_grid, 256>>>(nodes, u2e, w1, b1, V, N);

    int ntiles = (E + 15) / 16;
    int grid = 296;
    int maxgrid = (ntiles + 7) / 8;
    if (grid > maxgrid) grid = maxgrid;
    edge_mma_kernel<<<grid, 256>>>(neigh, seg, w2, b2, w3, b3, E, ntiles);

    agg_kernel<<<(N * 32 + 255) / 256, 256>>>(neigh, seg, u2e, (float*)d_out, N, E);
}